// round 1
// baseline (speedup 1.0000x reference)
#include <cuda_runtime.h>
#include <cstddef>

// ---------------------------------------------------------------------------
// CrossAgentAttention: B=1024, N=32, D=512, H=4, HD=128
//   qkv = x @ Win^T + bin          (32768 x 1536)
//   per (b,h): scores=QK^T/sqrt(128), mask diag+padding, softmax, ctx=attn@V
//   out = ctx @ Wout^T + bout      (32768 x 512)
// ---------------------------------------------------------------------------

#define Bdim 1024
#define Nag  32
#define Dm   512
#define Hh   4
#define HD   128
#define ROWS (Bdim * Nag)        // 32768
#define QKVW (3 * Dm)            // 1536

// Scratch (allocation-free rule: __device__ globals)
__device__ float g_qkv[(size_t)ROWS * QKVW];   // 192 MB
__device__ float g_ctx[(size_t)ROWS * Dm];     // 64 MB

// ---------------------------------------------------------------------------
// GEMM (NT): C[M,N] = A[M,K] @ B[N,K]^T + bias[N]
// Block tile 128x128, K-tile 16, 256 threads, 8x8 per-thread micro-tile.
// Assumes M%128==0, N%128==0, K%16==0 (true for both call sites).
// ---------------------------------------------------------------------------
#define BM 128
#define BN 128
#define BK 16
#define TM 8
#define TN 8

__global__ __launch_bounds__(256, 2)
void gemm_nt_bias(const float* __restrict__ A, const float* __restrict__ B,
                  const float* __restrict__ bias, float* __restrict__ C,
                  int M, int N, int K)
{
    __shared__ float As[BK][BM + 4];
    __shared__ float Bs[BK][BN + 4];

    const int tid = threadIdx.x;
    const int tx = tid & 15;          // 0..15 -> N direction
    const int ty = tid >> 4;          // 0..15 -> M direction

    const float* Ab = A + (size_t)blockIdx.y * BM * K;
    const float* Bb = B + (size_t)blockIdx.x * BN * K;

    float acc[TM][TN];
    #pragma unroll
    for (int i = 0; i < TM; i++)
        #pragma unroll
        for (int j = 0; j < TN; j++) acc[i][j] = 0.0f;

    for (int kk = 0; kk < K; kk += BK) {
        // Load 128x16 tiles of A and B (512 float4 each; 2 per thread)
        #pragma unroll
        for (int l = 0; l < 2; l++) {
            int f  = tid + l * 256;       // 0..511
            int r  = f >> 2;              // row 0..127
            int c4 = (f & 3) << 2;        // col 0,4,8,12
            float4 av = *(const float4*)(Ab + (size_t)r * K + kk + c4);
            As[c4 + 0][r] = av.x; As[c4 + 1][r] = av.y;
            As[c4 + 2][r] = av.z; As[c4 + 3][r] = av.w;
            float4 bv = *(const float4*)(Bb + (size_t)r * K + kk + c4);
            Bs[c4 + 0][r] = bv.x; Bs[c4 + 1][r] = bv.y;
            Bs[c4 + 2][r] = bv.z; Bs[c4 + 3][r] = bv.w;
        }
        __syncthreads();

        #pragma unroll
        for (int k = 0; k < BK; k++) {
            float a[TM], b[TN];
            #pragma unroll
            for (int i = 0; i < TM; i++) a[i] = As[k][ty * TM + i];
            #pragma unroll
            for (int j = 0; j < TN; j++) b[j] = Bs[k][tx * TN + j];
            #pragma unroll
            for (int i = 0; i < TM; i++)
                #pragma unroll
                for (int j = 0; j < TN; j++) acc[i][j] += a[i] * b[j];
        }
        __syncthreads();
    }

    const int row0 = blockIdx.y * BM + ty * TM;
    const int col0 = blockIdx.x * BN + tx * TN;
    float bz[TN];
    #pragma unroll
    for (int j = 0; j < TN; j++) bz[j] = bias[col0 + j];

    #pragma unroll
    for (int i = 0; i < TM; i++) {
        float4 v0, v1;
        v0.x = acc[i][0] + bz[0]; v0.y = acc[i][1] + bz[1];
        v0.z = acc[i][2] + bz[2]; v0.w = acc[i][3] + bz[3];
        v1.x = acc[i][4] + bz[4]; v1.y = acc[i][5] + bz[5];
        v1.z = acc[i][6] + bz[6]; v1.w = acc[i][7] + bz[7];
        float* cp = C + (size_t)(row0 + i) * N + col0;
        *(float4*)(cp)     = v0;
        *(float4*)(cp + 4) = v1;
    }
}

// ---------------------------------------------------------------------------
// Attention: one block per (b,h). 128 threads (4 warps).
// smem: qs[32][128], ks[32][129] (pad -> conflict-free), vs[32][128], s[32][33]
// ---------------------------------------------------------------------------
#define ATTN_SMEM_FLOATS (4096 + 32 * 129 + 4096 + 32 * 33)   // 13376
#define ATTN_SMEM_BYTES  (ATTN_SMEM_FLOATS * 4)               // 53504

__global__ __launch_bounds__(128)
void attn_kernel(const float* __restrict__ qkv,
                 const unsigned char* __restrict__ pad,
                 float* __restrict__ ctx)
{
    extern __shared__ float sm[];
    float* qs = sm;                 // [32][128]
    float* ks = sm + 4096;          // [32][129]
    float* vs = sm + 4096 + 32*129; // [32][128]
    float* s  = vs + 4096;          // [32][33]

    const int bh   = blockIdx.x;
    const int b    = bh >> 2;
    const int h    = bh & 3;
    const int tid  = threadIdx.x;
    const int warp = tid >> 5;
    const int lane = tid & 31;

    // --- stage Q/K/V for this (b,h) into smem -----------------------------
    for (int it = tid; it < Nag * 32; it += 128) {   // 1024 float4 per matrix
        int r  = it >> 5;            // agent row 0..31
        int c4 = (it & 31) << 2;     // 0..124
        const float* base = qkv + (size_t)(b * Nag + r) * QKVW + h * HD;
        float4 qv = *(const float4*)(base + c4);
        *(float4*)&qs[r * 128 + c4] = qv;
        float4 kv = *(const float4*)(base + 512 + c4);
        ks[r * 129 + c4 + 0] = kv.x; ks[r * 129 + c4 + 1] = kv.y;
        ks[r * 129 + c4 + 2] = kv.z; ks[r * 129 + c4 + 3] = kv.w;
        float4 vv = *(const float4*)(base + 1024 + c4);
        *(float4*)&vs[r * 128 + c4] = vv;
    }
    const bool pad_lane = (pad[b * Nag + lane] != 0);
    __syncthreads();

    // --- scores: warp w computes rows {w, w+4, ..., w+28}, lane = column j -
    const float SCALE = 0.08838834764831843f;  // 1/sqrt(128)
    const int j = lane;
    {
        float accr[8];
        #pragma unroll
        for (int ii = 0; ii < 8; ii++) accr[ii] = 0.0f;
        for (int dc = 0; dc < HD; dc += 16) {
            float kr[16];
            #pragma unroll
            for (int d = 0; d < 16; d++) kr[d] = ks[j * 129 + dc + d];
            #pragma unroll
            for (int ii = 0; ii < 8; ii++) {
                const int i = warp + 4 * ii;
                float a = 0.0f;
                #pragma unroll
                for (int d = 0; d < 16; d++) a += qs[i * 128 + dc + d] * kr[d];
                accr[ii] += a;
            }
        }
        #pragma unroll
        for (int ii = 0; ii < 8; ii++) {
            const int i = warp + 4 * ii;
            s[i * 33 + j] = accr[ii] * SCALE;
        }
    }
    __syncthreads();

    // --- masked softmax per row (warp per row group) ----------------------
    for (int i = warp; i < Nag; i += 4) {
        float v = s[i * 33 + lane];
        const bool masked = (lane == i) || pad_lane;
        v = masked ? -1.0e30f : v;
        float m = v;
        #pragma unroll
        for (int off = 16; off > 0; off >>= 1)
            m = fmaxf(m, __shfl_xor_sync(0xffffffffu, m, off));
        float p = masked ? 0.0f : __expf(v - m);
        float sum = p;
        #pragma unroll
        for (int off = 16; off > 0; off >>= 1)
            sum += __shfl_xor_sync(0xffffffffu, sum, off);
        s[i * 33 + lane] = p / sum;
    }
    __syncthreads();

    // --- ctx = attn @ V : thread t owns head-dim column d = t --------------
    const int d = tid;
    #pragma unroll 4
    for (int i = 0; i < Nag; i++) {
        float a = 0.0f;
        #pragma unroll
        for (int jj = 0; jj < Nag; jj++) a += s[i * 33 + jj] * vs[jj * 128 + d];
        ctx[(size_t)(b * Nag + i) * Dm + h * HD + d] = a;
    }
}

// ---------------------------------------------------------------------------
extern "C" void kernel_launch(void* const* d_in, const int* in_sizes, int n_in,
                              void* d_out, int out_size)
{
    const float*         x     = (const float*)d_in[0];
    const unsigned char* pad   = (const unsigned char*)d_in[1];
    const float*         w_in  = (const float*)d_in[2];
    const float*         b_in  = (const float*)d_in[3];
    const float*         w_out = (const float*)d_in[4];
    const float*         b_out = (const float*)d_in[5];
    float*               out   = (float*)d_out;

    void* qkv_p; cudaGetSymbolAddress(&qkv_p, g_qkv);
    void* ctx_p; cudaGetSymbolAddress(&ctx_p, g_ctx);
    float* qkv = (float*)qkv_p;
    float* ctx = (float*)ctx_p;

    static bool attr_set = false;
    // (idempotent, deterministic: same call every time; just avoid repeat API cost)
    if (!attr_set) {
        cudaFuncSetAttribute(attn_kernel,
                             cudaFuncAttributeMaxDynamicSharedMemorySize,
                             ATTN_SMEM_BYTES);
        attr_set = true;
    }

    // 1) QKV projection: (32768 x 512) @ (1536 x 512)^T
    gemm_nt_bias<<<dim3(QKVW / BN, ROWS / BM), 256>>>(x, w_in, b_in, qkv,
                                                      ROWS, QKVW, Dm);
    // 2) attention per (b, h)
    attn_kernel<<<Bdim * Hh, 128, ATTN_SMEM_BYTES>>>(qkv, pad, ctx);
    // 3) output projection: (32768 x 512) @ (512 x 512)^T
    gemm_nt_bias<<<dim3(Dm / BN, ROWS / BM), 256>>>(ctx, w_out, b_out, out,
                                                    ROWS, Dm, Dm);
}

// round 16
// speedup vs baseline: 2.5196x; 2.5196x over previous
#include <cuda_runtime.h>
#include <cstdint>
#include <cstddef>

// ---------------------------------------------------------------------------
// CrossAgentAttention: B=1024, N=32, D=512, H=4, HD=128
// GEMMs via mma.sync m16n8k8 tf32 (family-compatible tensor path — the
// harness compiles for base sm_103, which rejects tcgen05/TMEM).
// ---------------------------------------------------------------------------

#define Bdim 1024
#define Nag  32
#define Dm   512
#define Hh   4
#define HD   128
#define ROWS (Bdim * Nag)        // 32768
#define QKVW (3 * Dm)            // 1536
#define GK   512                 // K of both GEMMs

// Scratch (allocation-free rule: __device__ globals)
__device__ float g_qkv[(size_t)ROWS * QKVW];   // 192 MB
__device__ float g_ctx[(size_t)ROWS * Dm];     // 64 MB

__device__ __forceinline__ float tf32r(float x) {   // round-to-nearest tf32
    float r;
    asm("cvt.rna.tf32.f32 %0, %1;" : "=f"(r) : "f"(x));
    return r;
}

// d += a @ b  (m16n8k8, tf32 inputs, f32 accum)
__device__ __forceinline__ void mma_tf32(float* d, const uint32_t* a,
                                         const uint32_t* b) {
    asm volatile(
        "mma.sync.aligned.m16n8k8.row.col.f32.tf32.tf32.f32 "
        "{%0,%1,%2,%3}, {%4,%5,%6,%7}, {%8,%9}, {%0,%1,%2,%3};"
        : "+f"(d[0]), "+f"(d[1]), "+f"(d[2]), "+f"(d[3])
        : "r"(a[0]), "r"(a[1]), "r"(a[2]), "r"(a[3]), "r"(b[0]), "r"(b[1]));
}

// ---------------------------------------------------------------------------
// Tensor-core tf32 GEMM (NT): C[M,N] = A[M,512] @ B[N,512]^T + bias[N]
// Block 128x128x32, 256 threads (8 warps, 4x2), warp tile 32x64.
// Smem stride 36 floats -> conflict-free fragment loads ((4r+c)%32 distinct).
// ---------------------------------------------------------------------------
#define BM 128
#define BN 128
#define BK 32
#define KSTRIDE 36

__global__ __launch_bounds__(256, 2)
void gemm_mma_tf32(const float* __restrict__ A, const float* __restrict__ Bw,
                   const float* __restrict__ bias, float* __restrict__ C,
                   int N)
{
    __shared__ float As[BM][KSTRIDE];
    __shared__ float Bs[BN][KSTRIDE];

    const int tid = threadIdx.x;
    const int wid = tid >> 5, lane = tid & 31;
    const int bx = blockIdx.x, by = blockIdx.y;
    const int wm = (wid & 3) << 5;      // warp m offset: 0,32,64,96
    const int wn = (wid >> 2) << 6;     // warp n offset: 0,64
    const int gr = lane >> 2;           // fragment group row 0..7
    const int qc = lane & 3;            // fragment k quad 0..3

    const float* Ab = A  + (size_t)by * BM * GK;
    const float* Bb = Bw + (size_t)bx * BN * GK;

    float acc[2][8][4];
    #pragma unroll
    for (int mi = 0; mi < 2; mi++)
        #pragma unroll
        for (int ni = 0; ni < 8; ni++)
            #pragma unroll
            for (int q = 0; q < 4; q++) acc[mi][ni][q] = 0.0f;

    for (int t = 0; t < GK / BK; t++) {
        const int k0 = t * BK;
        // ---- stage 128x32 A and B tiles (cvt.rna during store) -----------
        #pragma unroll
        for (int i = 0; i < 4; i++) {
            const int f  = i * 256 + tid;     // 0..1023 float4 slots
            const int r  = f >> 3;            // row 0..127
            const int c4 = (f & 7) << 2;      // col 0,4,..,28
            float4 a4 = *(const float4*)(Ab + (size_t)r * GK + k0 + c4);
            As[r][c4 + 0] = tf32r(a4.x); As[r][c4 + 1] = tf32r(a4.y);
            As[r][c4 + 2] = tf32r(a4.z); As[r][c4 + 3] = tf32r(a4.w);
            float4 b4 = *(const float4*)(Bb + (size_t)r * GK + k0 + c4);
            Bs[r][c4 + 0] = tf32r(b4.x); Bs[r][c4 + 1] = tf32r(b4.y);
            Bs[r][c4 + 2] = tf32r(b4.z); Bs[r][c4 + 3] = tf32r(b4.w);
        }
        __syncthreads();

        // ---- 4 k-steps of 8 ---------------------------------------------
        #pragma unroll
        for (int ks = 0; ks < 4; ks++) {
            const int kk = ks * 8;
            uint32_t af[2][4], bf[8][2];
            #pragma unroll
            for (int mi = 0; mi < 2; mi++) {
                const int row = wm + mi * 16 + gr;
                af[mi][0] = __float_as_uint(As[row    ][kk + qc    ]);
                af[mi][1] = __float_as_uint(As[row + 8][kk + qc    ]);
                af[mi][2] = __float_as_uint(As[row    ][kk + qc + 4]);
                af[mi][3] = __float_as_uint(As[row + 8][kk + qc + 4]);
            }
            #pragma unroll
            for (int ni = 0; ni < 8; ni++) {
                const int col = wn + ni * 8 + gr;
                bf[ni][0] = __float_as_uint(Bs[col][kk + qc    ]);
                bf[ni][1] = __float_as_uint(Bs[col][kk + qc + 4]);
            }
            #pragma unroll
            for (int mi = 0; mi < 2; mi++)
                #pragma unroll
                for (int ni = 0; ni < 8; ni++)
                    mma_tf32(acc[mi][ni], af[mi], bf[ni]);
        }
        __syncthreads();
    }

    // ---- epilogue: d0,d1 -> (row, 2q..2q+1); d2,d3 -> (row+8, ...) -------
    #pragma unroll
    for (int mi = 0; mi < 2; mi++) {
        const int row = by * BM + wm + mi * 16 + gr;
        #pragma unroll
        for (int ni = 0; ni < 8; ni++) {
            const int col = bx * BN + wn + ni * 8 + qc * 2;
            const float b0 = bias[col], b1 = bias[col + 1];
            float2 v0 = { acc[mi][ni][0] + b0, acc[mi][ni][1] + b1 };
            float2 v1 = { acc[mi][ni][2] + b0, acc[mi][ni][3] + b1 };
            *(float2*)(C + (size_t)row * N + col)       = v0;
            *(float2*)(C + (size_t)(row + 8) * N + col) = v1;
        }
    }
}

// ---------------------------------------------------------------------------
// Attention: one block per (b,h). 128 threads (4 warps). fp32. (R1-proven)
// ---------------------------------------------------------------------------
#define ATTN_SMEM_FLOATS (4096 + 32 * 129 + 4096 + 32 * 33)
#define ATTN_SMEM_BYTES  (ATTN_SMEM_FLOATS * 4)               // 53504

__global__ __launch_bounds__(128)
void attn_kernel(const float* __restrict__ qkv,
                 const unsigned char* __restrict__ pad,
                 float* __restrict__ ctx)
{
    extern __shared__ float smf[];
    float* qs = smf;                 // [32][128]
    float* ks = smf + 4096;          // [32][129]
    float* vs = smf + 4096 + 32*129; // [32][128]
    float* s  = vs + 4096;           // [32][33]

    const int bh   = blockIdx.x;
    const int b    = bh >> 2;
    const int h    = bh & 3;
    const int tid  = threadIdx.x;
    const int warp = tid >> 5;
    const int lane = tid & 31;

    for (int it = tid; it < Nag * 32; it += 128) {
        int r  = it >> 5;
        int c4 = (it & 31) << 2;
        const float* base = qkv + (size_t)(b * Nag + r) * QKVW + h * HD;
        float4 qv = *(const float4*)(base + c4);
        *(float4*)&qs[r * 128 + c4] = qv;
        float4 kv = *(const float4*)(base + 512 + c4);
        ks[r * 129 + c4 + 0] = kv.x; ks[r * 129 + c4 + 1] = kv.y;
        ks[r * 129 + c4 + 2] = kv.z; ks[r * 129 + c4 + 3] = kv.w;
        float4 vv = *(const float4*)(base + 1024 + c4);
        *(float4*)&vs[r * 128 + c4] = vv;
    }
    const bool pad_lane = (pad[b * Nag + lane] != 0);
    __syncthreads();

    const float SCALE = 0.08838834764831843f;  // 1/sqrt(128)
    const int j = lane;
    {
        float accr[8];
        #pragma unroll
        for (int ii = 0; ii < 8; ii++) accr[ii] = 0.0f;
        for (int dc = 0; dc < HD; dc += 16) {
            float kr[16];
            #pragma unroll
            for (int d = 0; d < 16; d++) kr[d] = ks[j * 129 + dc + d];
            #pragma unroll
            for (int ii = 0; ii < 8; ii++) {
                const int i = warp + 4 * ii;
                float a = 0.0f;
                #pragma unroll
                for (int d = 0; d < 16; d++) a += qs[i * 128 + dc + d] * kr[d];
                accr[ii] += a;
            }
        }
        #pragma unroll
        for (int ii = 0; ii < 8; ii++) {
            const int i = warp + 4 * ii;
            s[i * 33 + j] = accr[ii] * SCALE;
        }
    }
    __syncthreads();

    for (int i = warp; i < Nag; i += 4) {
        float v = s[i * 33 + lane];
        const bool masked = (lane == i) || pad_lane;
        v = masked ? -1.0e30f : v;
        float m = v;
        #pragma unroll
        for (int off = 16; off > 0; off >>= 1)
            m = fmaxf(m, __shfl_xor_sync(0xffffffffu, m, off));
        float p = masked ? 0.0f : __expf(v - m);
        float sum = p;
        #pragma unroll
        for (int off = 16; off > 0; off >>= 1)
            sum += __shfl_xor_sync(0xffffffffu, sum, off);
        s[i * 33 + lane] = p / sum;
    }
    __syncthreads();

    const int d = tid;
    #pragma unroll 4
    for (int i = 0; i < Nag; i++) {
        float a = 0.0f;
        #pragma unroll
        for (int jj = 0; jj < Nag; jj++) a += s[i * 33 + jj] * vs[jj * 128 + d];
        ctx[(size_t)(b * Nag + i) * Dm + h * HD + d] = a;
    }
}

// ---------------------------------------------------------------------------
extern "C" void kernel_launch(void* const* d_in, const int* in_sizes, int n_in,
                              void* d_out, int out_size)
{
    const float*         x     = (const float*)d_in[0];
    const unsigned char* pad   = (const unsigned char*)d_in[1];
    const float*         w_in  = (const float*)d_in[2];
    const float*         b_in  = (const float*)d_in[3];
    const float*         w_out = (const float*)d_in[4];
    const float*         b_out = (const float*)d_in[5];
    float*               out   = (float*)d_out;

    void* qkv_p; cudaGetSymbolAddress(&qkv_p, g_qkv);
    void* ctx_p; cudaGetSymbolAddress(&ctx_p, g_ctx);
    float* qkv = (float*)qkv_p;
    float* ctx = (float*)ctx_p;

    static bool attr_set = false;
    if (!attr_set) {
        cudaFuncSetAttribute(attn_kernel,
                             cudaFuncAttributeMaxDynamicSharedMemorySize,
                             ATTN_SMEM_BYTES);
        attr_set = true;
    }

    // 1) QKV projection: (32768 x 512) @ (1536 x 512)^T
    gemm_mma_tf32<<<dim3(QKVW / BN, ROWS / BM), 256>>>(x, w_in, b_in, qkv,
                                                       QKVW);
    // 2) attention per (b, h)
    attn_kernel<<<Bdim * Hh, 128, ATTN_SMEM_BYTES>>>(qkv, pad, ctx);
    // 3) output projection: (32768 x 512) @ (512 x 512)^T
    gemm_mma_tf32<<<dim3(Dm / BN, ROWS / BM), 256>>>(ctx, w_out, b_out, out,
                                                     Dm);
}